// round 15
// baseline (speedup 1.0000x reference)
#include <cuda_runtime.h>
#include <cuda_bf16.h>
#include <cstdint>

// GCN, 4 layers: h' = relu( D^-1/2 (A+I) D^-1/2 (h W) + b )
// All GEMMs on mma.sync bf16x3 (D = AhBh+AhBl+AlBh, fp32 accum, ~6e-6 err).
// W fragments pre-converted once (k_init). The CSR gather applies
// relu(agg*dinv+bias), splits to bf16 hi/lo and writes the NEXT layer's
// A-FRAGMENTS directly -> follow-on GEMMs (k_gemm_frag) are pure LDG + MMA.
// Layer-0 GEMM converts raw x to fragments IN REGISTERS (sector-aligned
// float2 loads), no smem / no syncthreads.

#define NN 100000
#define EE 500000
#define FD 128
#define NBLK 782  // ceil(NN/128)

__device__ float g_dinv[NN];
__device__ float g_g[(size_t)NN * FD];
// CSR (dst-major)
__device__ int g_cnt[NN];
__device__ int g_rowptr[NN + 1];
__device__ int g_fill[NN];
__device__ int g_eidx[EE];
__device__ int g_bsums[256];
// W fragments (hi/lo): 3 wide layers x 8192, narrow 4096
__device__ uint32_t g_wfh[3][8192];
__device__ uint32_t g_wfl[3][8192];
__device__ uint32_t g_w3h[4096];
__device__ uint32_t g_w3l[4096];
// A fragments written by the gather (zero-init covers pad rows)
__device__ uint32_t g_afh[(size_t)NBLK * 8192];
__device__ uint32_t g_afl[(size_t)NBLK * 8192];

// ---------------- fragment layout ----------------
//   A: [mtile 8][ktile 8][lane 32][j 4]   (m16k16 row-major A fragment)
//   B: [ktile 8][ntile NT][lane 32][j 2]  (k16n8 col-major B fragment)
#define A_FRAG(mt, kt, lane, j) ((((mt) * 8 + (kt)) * 32 + (lane)) * 4 + (j))

__device__ __forceinline__ uint32_t pack_bf16(float x, float y) {
  __nv_bfloat162 p = __floats2bfloat162_rn(x, y);  // x -> low half
  return *(uint32_t*)&p;
}

__device__ __forceinline__ void mma_bf16(float* c, const uint32_t* a,
                                         const uint32_t* b) {
  asm volatile(
      "mma.sync.aligned.m16n8k16.row.col.f32.bf16.bf16.f32 "
      "{%0,%1,%2,%3}, {%4,%5,%6,%7}, {%8,%9}, {%0,%1,%2,%3};"
      : "+f"(c[0]), "+f"(c[1]), "+f"(c[2]), "+f"(c[3])
      : "r"(a[0]), "r"(a[1]), "r"(a[2]), "r"(a[3]), "r"(b[0]), "r"(b[1]));
}

// split a float2 (k-consecutive pair) into packed hi / lo bf16x2
__device__ __forceinline__ void split2(float2 v, uint32_t& hi, uint32_t& lo) {
  __nv_bfloat16 h0 = __float2bfloat16(v.x), h1 = __float2bfloat16(v.y);
  float l0 = v.x - __bfloat162float(h0), l1 = v.y - __bfloat162float(h1);
  hi = pack_bf16(__bfloat162float(h0), __bfloat162float(h1));
  lo = pack_bf16(l0, l1);
}

// ---------------- init: W fragment prep + cnt zeroing (fused) ----------------

__global__ void k_init(const float* __restrict__ W0, const float* __restrict__ W1,
                       const float* __restrict__ W2, const float* __restrict__ W3,
                       int n) {
  int idx = blockIdx.x * blockDim.x + threadIdx.x;
  if (idx < 28672) {
    int D, NT, lidx;
    const float* W;
    uint32_t *fh, *fl;
    if (idx < 24576) {
      int l = idx >> 13;
      lidx = idx & 8191;
      D = 128; NT = 16;
      W = (l == 0) ? W0 : (l == 1) ? W1 : W2;
      fh = g_wfh[l]; fl = g_wfl[l];
    } else {
      lidx = idx - 24576;
      D = 40; NT = 8;
      W = W3;
      fh = g_w3h; fl = g_w3l;
    }
    int ncols = NT * 8;
    int nn = lidx % ncols;
    int kp = lidx / ncols;  // k pair 0..63
    float2 v = make_float2(0.f, 0.f);
    if (nn < D) {
      v.x = W[(size_t)(2 * kp) * D + nn];
      v.y = W[(size_t)(2 * kp + 1) * D + nn];
    }
    uint32_t hi, lo;
    split2(v, hi, lo);
    int kt = kp >> 3;
    int lane = (nn & 7) * 4 + (kp & 3);
    int j = (kp >> 2) & 1;
    int slot = (((kt * NT) + (nn >> 3)) * 32 + lane) * 2 + j;
    fh[slot] = hi;
    fl[slot] = lo;
  } else {
    int i = idx - 28672;
    if (i < n) g_cnt[i] = 0;
  }
}

// ---------------- degree + CSR build ----------------

__global__ void k_count(const int* __restrict__ dst, int e) {
  int i = blockIdx.x * blockDim.x + threadIdx.x;
  if (i < e) atomicAdd(&g_cnt[dst[i]], 1);
}
__global__ void k_dinv(int n) {
  int i = blockIdx.x * blockDim.x + threadIdx.x;
  if (i < n) g_dinv[i] = rsqrtf((float)(1 + g_cnt[i]));  // +1 self loop
}

#define SCAN_B 512
__global__ void k_scan1(int n) {  // block-local inclusive scan -> rowptr[i+1]
  __shared__ int sm[SCAN_B];
  int i = blockIdx.x * SCAN_B + threadIdx.x;
  sm[threadIdx.x] = (i < n) ? g_cnt[i] : 0;
  __syncthreads();
  for (int off = 1; off < SCAN_B; off <<= 1) {
    int t = (threadIdx.x >= off) ? sm[threadIdx.x - off] : 0;
    __syncthreads();
    sm[threadIdx.x] += t;
    __syncthreads();
  }
  if (i < n) g_rowptr[i + 1] = sm[threadIdx.x];
  if (threadIdx.x == SCAN_B - 1) g_bsums[blockIdx.x] = sm[threadIdx.x];
  if (i == 0) g_rowptr[0] = 0;
}

// scan2+scan3 merged: each block reduces its own bsums prefix inline.
__global__ void k_scan23(int n) {
  __shared__ int red[256];
  __shared__ int base_sh;
  int t = threadIdx.x;
  if (t < 256) red[t] = (t < (int)blockIdx.x) ? g_bsums[t] : 0;
  __syncthreads();
#pragma unroll
  for (int off = 128; off > 0; off >>= 1) {
    if (t < off) red[t] += red[t + off];
    __syncthreads();
  }
  if (t == 0) base_sh = red[0];
  __syncthreads();
  int base = base_sh;
  int i = blockIdx.x * SCAN_B + t;
  if (i < n) {
    int v = g_rowptr[i + 1] + base;
    g_rowptr[i + 1] = v;
    if (i + 1 < n) g_fill[i + 1] = v;  // fill[i] = rowptr[i]
    if (i == 0) g_fill[0] = 0;
  }
}
__global__ void k_fill(const int* __restrict__ src, const int* __restrict__ dst,
                       int e) {
  int i = blockIdx.x * blockDim.x + threadIdx.x;
  if (i < e) {
    int p = atomicAdd(&g_fill[dst[i]], 1);
    g_eidx[p] = src[i];
  }
}

// ---------------- layer-0 GEMM: convert x -> fragments IN REGISTERS ---------
// Thread lane's A-frag regs for (mi,kt) are float2s of x at rows r0,r0+8 and
// cols kc,kc+8 (kc = kt*16 + (lane&3)*2). Lanes 0-3 per row-group read one
// contiguous 32B sector. No smem, no syncthreads.

__global__ __launch_bounds__(256, 2)
void k_gemm_l0(const float* __restrict__ A, const uint32_t* __restrict__ Bh,
               const uint32_t* __restrict__ Bl, int M) {
  const int tid = threadIdx.x;
  const int wid = tid >> 5;
  const int lane = tid & 31;
  const int bm = blockIdx.x * 128;
  const int mw = wid & 3;
  const int nw = wid >> 2;

  const int rbase = bm + mw * 32 + (lane >> 2);
  const int kcbase = (lane & 3) * 2;
  const float2 z2 = make_float2(0.f, 0.f);

  float c[2][8][4];
#pragma unroll
  for (int mi = 0; mi < 2; mi++)
#pragma unroll
    for (int nt = 0; nt < 8; nt++)
#pragma unroll
      for (int q = 0; q < 4; q++) c[mi][nt][q] = 0.f;

#pragma unroll
  for (int kt = 0; kt < 8; kt++) {
    uint32_t ah[2][4], al_[2][4];
#pragma unroll
    for (int mi = 0; mi < 2; mi++) {
      int r0 = rbase + mi * 16;
      int r1 = r0 + 8;
      int kc = kt * 16 + kcbase;
      float2 v00 = (r0 < M) ? *(const float2*)(A + (size_t)r0 * 128 + kc) : z2;
      float2 v10 = (r1 < M) ? *(const float2*)(A + (size_t)r1 * 128 + kc) : z2;
      float2 v01 = (r0 < M) ? *(const float2*)(A + (size_t)r0 * 128 + kc + 8) : z2;
      float2 v11 = (r1 < M) ? *(const float2*)(A + (size_t)r1 * 128 + kc + 8) : z2;
      split2(v00, ah[mi][0], al_[mi][0]);
      split2(v10, ah[mi][1], al_[mi][1]);
      split2(v01, ah[mi][2], al_[mi][2]);
      split2(v11, ah[mi][3], al_[mi][3]);
    }
#pragma unroll
    for (int nh = 0; nh < 2; nh++) {
      uint32_t bh[4][2], bl_[4][2];
#pragma unroll
      for (int nt = 0; nt < 4; nt++) {
        int ntile = nw * 8 + nh * 4 + nt;
        int slot = ((kt * 16 + ntile) * 32 + lane) * 2;
        *(uint2*)bh[nt]  = __ldg((const uint2*)&Bh[slot]);
        *(uint2*)bl_[nt] = __ldg((const uint2*)&Bl[slot]);
      }
#pragma unroll
      for (int mi = 0; mi < 2; mi++)
#pragma unroll
        for (int nt = 0; nt < 4; nt++) {
          float* cc = c[mi][nh * 4 + nt];
          mma_bf16(cc, ah[mi], bh[nt]);
          mma_bf16(cc, ah[mi], bl_[nt]);
          mma_bf16(cc, al_[mi], bh[nt]);
        }
    }
  }

#pragma unroll
  for (int mi = 0; mi < 2; mi++) {
    int r0 = bm + mw * 32 + mi * 16 + (lane >> 2);
    int r1 = r0 + 8;
    float s0 = (r0 < M) ? g_dinv[r0] : 0.f;
    float s1 = (r1 < M) ? g_dinv[r1] : 0.f;
#pragma unroll
    for (int nt = 0; nt < 8; nt++) {
      int col = (nw * 8 + nt) * 8 + (lane & 3) * 2;
      if (r0 < M)
        *(float2*)(g_g + (size_t)r0 * 128 + col) =
            make_float2(c[mi][nt][0] * s0, c[mi][nt][1] * s0);
      if (r1 < M)
        *(float2*)(g_g + (size_t)r1 * 128 + col) =
            make_float2(c[mi][nt][2] * s1, c[mi][nt][3] * s1);
    }
  }
}

// ---------------- fragment-input GEMM (layers 1..3): no smem, no sync ------

template <int NT, int DOUT>
__global__ __launch_bounds__(256, 2)
void k_gemm_frag(const uint32_t* __restrict__ Bh, const uint32_t* __restrict__ Bl,
                 int M) {
  const int tid = threadIdx.x;
  const int wid = tid >> 5;
  const int lane = tid & 31;
  const int bm = blockIdx.x * 128;
  const uint32_t* Afh = g_afh + (size_t)blockIdx.x * 8192;
  const uint32_t* Afl = g_afl + (size_t)blockIdx.x * 8192;
  constexpr int WNT = NT / 2;

  const int mw = wid & 3;
  const int nw = wid >> 2;
  float c[2][WNT][4];
#pragma unroll
  for (int mi = 0; mi < 2; mi++)
#pragma unroll
    for (int nt = 0; nt < WNT; nt++)
#pragma unroll
      for (int q = 0; q < 4; q++) c[mi][nt][q] = 0.f;

#pragma unroll
  for (int kt = 0; kt < 8; kt++) {
    uint32_t ah[2][4], al_[2][4];
#pragma unroll
    for (int mi = 0; mi < 2; mi++) {
      int slot = A_FRAG(mw * 2 + mi, kt, lane, 0);
      *(uint4*)ah[mi]  = __ldg((const uint4*)&Afh[slot]);
      *(uint4*)al_[mi] = __ldg((const uint4*)&Afl[slot]);
    }
#pragma unroll
    for (int nh = 0; nh < WNT / 4; nh++) {
      uint32_t bh[4][2], bl_[4][2];
#pragma unroll
      for (int nt = 0; nt < 4; nt++) {
        int ntile = nw * WNT + nh * 4 + nt;
        int slot = ((kt * NT + ntile) * 32 + lane) * 2;
        *(uint2*)bh[nt]  = __ldg((const uint2*)&Bh[slot]);
        *(uint2*)bl_[nt] = __ldg((const uint2*)&Bl[slot]);
      }
#pragma unroll
      for (int mi = 0; mi < 2; mi++)
#pragma unroll
        for (int nt = 0; nt < 4; nt++) {
          float* cc = c[mi][nh * 4 + nt];
          mma_bf16(cc, ah[mi], bh[nt]);
          mma_bf16(cc, ah[mi], bl_[nt]);
          mma_bf16(cc, al_[mi], bh[nt]);
        }
    }
  }

#pragma unroll
  for (int mi = 0; mi < 2; mi++) {
    int r0 = bm + mw * 32 + mi * 16 + (lane >> 2);
    int r1 = r0 + 8;
    float s0 = (r0 < M) ? g_dinv[r0] : 0.f;
    float s1 = (r1 < M) ? g_dinv[r1] : 0.f;
#pragma unroll
    for (int nt = 0; nt < WNT; nt++) {
      int col = (nw * WNT + nt) * 8 + (lane & 3) * 2;
      if (col >= DOUT) continue;
      if (r0 < M)
        *(float2*)(g_g + (size_t)r0 * DOUT + col) =
            make_float2(c[mi][nt][0] * s0, c[mi][nt][1] * s0);
      if (r1 < M)
        *(float2*)(g_g + (size_t)r1 * DOUT + col) =
            make_float2(c[mi][nt][2] * s1, c[mi][nt][3] * s1);
    }
  }
}

// ---------------- CSR gather -> next layer's A fragments ----------------

__global__ void k_gather_frag(const float* __restrict__ bias, int n) {
  int w    = (blockIdx.x * blockDim.x + threadIdx.x) >> 5;
  int lane = threadIdx.x & 31;
  if (w >= n) return;
  int beg = __ldg(g_rowptr + w);
  int end = __ldg(g_rowptr + w + 1);
  float4 acc = *(const float4*)(g_g + (size_t)w * 128 + lane * 4);
  int e = beg;
  for (; e + 4 <= end; e += 4) {
    int s0 = __ldg(g_eidx + e);
    int s1 = __ldg(g_eidx + e + 1);
    int s2 = __ldg(g_eidx + e + 2);
    int s3 = __ldg(g_eidx + e + 3);
    float4 v0 = __ldg((const float4*)(g_g + (size_t)s0 * 128 + lane * 4));
    float4 v1 = __ldg((const float4*)(g_g + (size_t)s1 * 128 + lane * 4));
    float4 v2 = __ldg((const float4*)(g_g + (size_t)s2 * 128 + lane * 4));
    float4 v3 = __ldg((const float4*)(g_g + (size_t)s3 * 128 + lane * 4));
    acc.x += v0.x; acc.y += v0.y; acc.z += v0.z; acc.w += v0.w;
    acc.x += v1.x; acc.y += v1.y; acc.z += v1.z; acc.w += v1.w;
    acc.x += v2.x; acc.y += v2.y; acc.z += v2.z; acc.w += v2.w;
    acc.x += v3.x; acc.y += v3.y; acc.z += v3.z; acc.w += v3.w;
  }
  for (; e < end; e++) {
    int s = __ldg(g_eidx + e);
    float4 v = __ldg((const float4*)(g_g + (size_t)s * 128 + lane * 4));
    acc.x += v.x; acc.y += v.y; acc.z += v.z; acc.w += v.w;
  }
  float sc = g_dinv[w];
  float4 b = *(const float4*)(bias + lane * 4);
  float h0 = fmaxf(acc.x * sc + b.x, 0.f);
  float h1 = fmaxf(acc.y * sc + b.y, 0.f);
  float h2 = fmaxf(acc.z * sc + b.z, 0.f);
  float h3 = fmaxf(acc.w * sc + b.w, 0.f);
  uint32_t hA, lA, hB, lB;
  split2(make_float2(h0, h1), hA, lA);
  split2(make_float2(h2, h3), hB, lB);
  int block = w >> 7, mloc = w & 127;
  int r = mloc & 15, mt = mloc >> 4;
  int kt = lane >> 2;
  int fl0 = (r & 7) * 4 + ((2 * lane) & 3);
  int j = (r >> 3) + ((lane >> 1) & 1) * 2;
  size_t slot0 = (size_t)block * 8192 + A_FRAG(mt, kt, fl0, j);
  g_afh[slot0]     = hA;
  g_afh[slot0 + 4] = hB;
  g_afl[slot0]     = lA;
  g_afl[slot0 + 4] = lB;
}

// last layer (D=40): gather + finalize fused, 10 threads/node -> d_out.
__global__ void k_gather_out(const float* __restrict__ bias,
                             float* __restrict__ out, int n) {
  int t    = blockIdx.x * blockDim.x + threadIdx.x;
  int node = t / 10;
  int lane = t - node * 10;
  if (node >= n) return;
  int c = lane * 4;
  int beg = __ldg(g_rowptr + node);
  int end = __ldg(g_rowptr + node + 1);
  float4 acc = *(const float4*)(g_g + (size_t)node * 40 + c);
  int e = beg;
  for (; e + 4 <= end; e += 4) {
    int s0 = __ldg(g_eidx + e);
    int s1 = __ldg(g_eidx + e + 1);
    int s2 = __ldg(g_eidx + e + 2);
    int s3 = __ldg(g_eidx + e + 3);
    float4 v0 = __ldg((const float4*)(g_g + (size_t)s0 * 40 + c));
    float4 v1 = __ldg((const float4*)(g_g + (size_t)s1 * 40 + c));
    float4 v2 = __ldg((const float4*)(g_g + (size_t)s2 * 40 + c));
    float4 v3 = __ldg((const float4*)(g_g + (size_t)s3 * 40 + c));
    acc.x += v0.x; acc.y += v0.y; acc.z += v0.z; acc.w += v0.w;
    acc.x += v1.x; acc.y += v1.y; acc.z += v1.z; acc.w += v1.w;
    acc.x += v2.x; acc.y += v2.y; acc.z += v2.z; acc.w += v2.w;
    acc.x += v3.x; acc.y += v3.y; acc.z += v3.z; acc.w += v3.w;
  }
  for (; e < end; e++) {
    int s = __ldg(g_eidx + e);
    float4 v = __ldg((const float4*)(g_g + (size_t)s * 40 + c));
    acc.x += v.x; acc.y += v.y; acc.z += v.z; acc.w += v.w;
  }
  float sc = g_dinv[node];
  float4 b = *(const float4*)(bias + c);
  acc.x = acc.x * sc + b.x;
  acc.y = acc.y * sc + b.y;
  acc.z = acc.z * sc + b.z;
  acc.w = acc.w * sc + b.w;
  *(float4*)(out + (size_t)node * 40 + c) = acc;
}

// ---------------- host launcher ----------------

extern "C" void kernel_launch(void* const* d_in, const int* in_sizes, int n_in,
                              void* d_out, int out_size) {
  const float* x  = (const float*)d_in[0];
  const int*   ei = (const int*)d_in[1];
  const float* W[4] = {(const float*)d_in[2], (const float*)d_in[4],
                       (const float*)d_in[6], (const float*)d_in[8]};
  const float* b[4] = {(const float*)d_in[3], (const float*)d_in[5],
                       (const float*)d_in[7], (const float*)d_in[9]};

  int M = in_sizes[0] / FD;  // 100000
  int E = in_sizes[1] / 2;   // 500000
  const int* src = ei;
  const int* dst = ei + E;

  uint32_t *wfh, *wfl, *w3h, *w3l;
  cudaGetSymbolAddress((void**)&wfh, g_wfh);
  cudaGetSymbolAddress((void**)&wfl, g_wfl);
  cudaGetSymbolAddress((void**)&w3h, g_w3h);
  cudaGetSymbolAddress((void**)&w3l, g_w3l);

  int nscan = (M + SCAN_B - 1) / SCAN_B;  // 196
  int GB = (M + 127) / 128;               // 782
  int gatherB = (M * 32 + 255) / 256;     // 12500
  int initB = (28672 + M + 255) / 256;

  // 1: W frags + zero cnt
  k_init<<<initB, 256>>>(W[0], W[1], W[2], W[3], M);
  // 2: degree count
  k_count<<<(E + 255) / 256, 256>>>(dst, E);
  // 3: dinv
  k_dinv<<<(M + 255) / 256, 256>>>(M);
  // 4: layer-0 GEMM  (ncu profiles launch #4)
  k_gemm_l0<<<GB, 256>>>(x, wfh, wfl, M);
  // 5-7: CSR build
  k_scan1<<<nscan, SCAN_B>>>(M);
  k_scan23<<<nscan, SCAN_B>>>(M);
  k_fill<<<(E + 255) / 256, 256>>>(src, dst, E);

  // layer 0 aggregate -> A frags for layer 1
  k_gather_frag<<<gatherB, 256>>>(b[0], M);
  // layers 1-2
  k_gemm_frag<16, 128><<<GB, 256>>>(wfh + 8192, wfl + 8192, M);
  k_gather_frag<<<gatherB, 256>>>(b[1], M);
  k_gemm_frag<16, 128><<<GB, 256>>>(wfh + 16384, wfl + 16384, M);
  k_gather_frag<<<gatherB, 256>>>(b[2], M);
  // layer 3: D=40 frag GEMM + fused gather/finalize -> d_out
  k_gemm_frag<8, 40><<<GB, 256>>>(w3h, w3l, M);
  k_gather_out<<<(M * 10 + 255) / 256, 256>>>(b[3], (float*)d_out, M);
}

// round 16
// speedup vs baseline: 1.0340x; 1.0340x over previous
#include <cuda_runtime.h>
#include <cuda_bf16.h>
#include <cstdint>

// GCN, 4 layers: h' = relu( D^-1/2 (A+I) D^-1/2 (h W) + b )
// All GEMMs on mma.sync bf16x3 (D = AhBh+AhBl+AlBh, fp32 accum, ~6e-6 err).
// W fragments pre-converted once (k_init). The CSR gather applies
// relu(agg*dinv+bias), splits to bf16 hi/lo and writes the NEXT layer's
// A-FRAGMENTS directly -> follow-on GEMMs (k_gemm_frag) are pure LDG + MMA.
// Layer-0 GEMM stages A through smem (cross-warp reuse; batched convert).

#define NN 100000
#define EE 500000
#define FD 128
#define NBLK 782  // ceil(NN/128)

__device__ float g_dinv[NN];
__device__ float g_g[(size_t)NN * FD];
// CSR (dst-major)
__device__ int g_cnt[NN];
__device__ int g_rowptr[NN + 1];
__device__ int g_fill[NN];
__device__ int g_eidx[EE];
__device__ int g_bsums[256];
// W fragments (hi/lo): 3 wide layers x 8192, narrow 4096
__device__ uint32_t g_wfh[3][8192];
__device__ uint32_t g_wfl[3][8192];
__device__ uint32_t g_w3h[4096];
__device__ uint32_t g_w3l[4096];
// A fragments written by the gather (zero-init covers pad rows)
__device__ uint32_t g_afh[(size_t)NBLK * 8192];
__device__ uint32_t g_afl[(size_t)NBLK * 8192];

// ---------------- fragment layout ----------------
//   A: [mtile 8][ktile 8][lane 32][j 4]   (m16k16 row-major A fragment)
//   B: [ktile 8][ntile NT][lane 32][j 2]  (k16n8 col-major B fragment)
#define A_FRAG(mt, kt, lane, j) ((((mt) * 8 + (kt)) * 32 + (lane)) * 4 + (j))

__device__ __forceinline__ uint32_t pack_bf16(float x, float y) {
  __nv_bfloat162 p = __floats2bfloat162_rn(x, y);  // x -> low half
  return *(uint32_t*)&p;
}

__device__ __forceinline__ void mma_bf16(float* c, const uint32_t* a,
                                         const uint32_t* b) {
  asm volatile(
      "mma.sync.aligned.m16n8k16.row.col.f32.bf16.bf16.f32 "
      "{%0,%1,%2,%3}, {%4,%5,%6,%7}, {%8,%9}, {%0,%1,%2,%3};"
      : "+f"(c[0]), "+f"(c[1]), "+f"(c[2]), "+f"(c[3])
      : "r"(a[0]), "r"(a[1]), "r"(a[2]), "r"(a[3]), "r"(b[0]), "r"(b[1]));
}

// split a float2 (k-consecutive pair) into packed hi / lo bf16x2
__device__ __forceinline__ void split2(float2 v, uint32_t& hi, uint32_t& lo) {
  __nv_bfloat16 h0 = __float2bfloat16(v.x), h1 = __float2bfloat16(v.y);
  float l0 = v.x - __bfloat162float(h0), l1 = v.y - __bfloat162float(h1);
  hi = pack_bf16(__bfloat162float(h0), __bfloat162float(h1));
  lo = pack_bf16(l0, l1);
}

// ---------------- init: W fragment prep + cnt zeroing (fused) ----------------

__global__ void k_init(const float* __restrict__ W0, const float* __restrict__ W1,
                       const float* __restrict__ W2, const float* __restrict__ W3,
                       int n) {
  int idx = blockIdx.x * blockDim.x + threadIdx.x;
  if (idx < 28672) {
    int D, NT, lidx;
    const float* W;
    uint32_t *fh, *fl;
    if (idx < 24576) {
      int l = idx >> 13;
      lidx = idx & 8191;
      D = 128; NT = 16;
      W = (l == 0) ? W0 : (l == 1) ? W1 : W2;
      fh = g_wfh[l]; fl = g_wfl[l];
    } else {
      lidx = idx - 24576;
      D = 40; NT = 8;
      W = W3;
      fh = g_w3h; fl = g_w3l;
    }
    int ncols = NT * 8;
    int nn = lidx % ncols;
    int kp = lidx / ncols;  // k pair 0..63
    float2 v = make_float2(0.f, 0.f);
    if (nn < D) {
      v.x = W[(size_t)(2 * kp) * D + nn];
      v.y = W[(size_t)(2 * kp + 1) * D + nn];
    }
    uint32_t hi, lo;
    split2(v, hi, lo);
    int kt = kp >> 3;
    int lane = (nn & 7) * 4 + (kp & 3);
    int j = (kp >> 2) & 1;
    int slot = (((kt * NT) + (nn >> 3)) * 32 + lane) * 2 + j;
    fh[slot] = hi;
    fl[slot] = lo;
  } else {
    int i = idx - 28672;
    if (i < n) g_cnt[i] = 0;
  }
}

// ---------------- degree + CSR build ----------------

__global__ void k_count(const int* __restrict__ dst, int e) {
  int i = blockIdx.x * blockDim.x + threadIdx.x;
  if (i < e) atomicAdd(&g_cnt[dst[i]], 1);
}

#define SCAN_B 512
__global__ void k_scan1(int n) {  // block scan -> rowptr[i+1]; also dinv
  __shared__ int sm[SCAN_B];
  int i = blockIdx.x * SCAN_B + threadIdx.x;
  int cnt = (i < n) ? g_cnt[i] : 0;
  if (i < n) g_dinv[i] = rsqrtf((float)(1 + cnt));  // +1 self loop
  sm[threadIdx.x] = cnt;
  __syncthreads();
  for (int off = 1; off < SCAN_B; off <<= 1) {
    int t = (threadIdx.x >= off) ? sm[threadIdx.x - off] : 0;
    __syncthreads();
    sm[threadIdx.x] += t;
    __syncthreads();
  }
  if (i < n) g_rowptr[i + 1] = sm[threadIdx.x];
  if (threadIdx.x == SCAN_B - 1) g_bsums[blockIdx.x] = sm[threadIdx.x];
  if (i == 0) g_rowptr[0] = 0;
}

// scan2+scan3 merged: each block reduces its own bsums prefix inline.
__global__ void k_scan23(int n) {
  __shared__ int red[256];
  __shared__ int base_sh;
  int t = threadIdx.x;
  if (t < 256) red[t] = (t < (int)blockIdx.x) ? g_bsums[t] : 0;
  __syncthreads();
#pragma unroll
  for (int off = 128; off > 0; off >>= 1) {
    if (t < off) red[t] += red[t + off];
    __syncthreads();
  }
  if (t == 0) base_sh = red[0];
  __syncthreads();
  int base = base_sh;
  int i = blockIdx.x * SCAN_B + t;
  if (i < n) {
    int v = g_rowptr[i + 1] + base;
    g_rowptr[i + 1] = v;
    if (i + 1 < n) g_fill[i + 1] = v;  // fill[i] = rowptr[i]
    if (i == 0) g_fill[0] = 0;
  }
}
__global__ void k_fill(const int* __restrict__ src, const int* __restrict__ dst,
                       int e) {
  int i = blockIdx.x * blockDim.x + threadIdx.x;
  if (i < e) {
    int p = atomicAdd(&g_fill[dst[i]], 1);
    g_eidx[p] = src[i];
  }
}

// ---------------- layer-0 GEMM (smem staging, batched convert) ----------------

__global__ __launch_bounds__(256, 2)
void k_gemm_l0(const float* __restrict__ A, const uint32_t* __restrict__ Bh,
               const uint32_t* __restrict__ Bl, int M) {
  extern __shared__ uint32_t sm[];
  uint32_t* sAh = sm;  // 8192 u32
  uint32_t* sAl = sm + 8192;

  const int tid = threadIdx.x;
  const int wid = tid >> 5;
  const int lane = tid & 31;
  const int bm = blockIdx.x * 128;

#pragma unroll
  for (int it = 0; it < 32; it++) {
    int idx = it * 256 + tid;
    int m = idx >> 6;
    int kp = idx & 63;
    int arow = bm + m;
    float2 v = make_float2(0.f, 0.f);
    if (arow < M) v = *(const float2*)(A + (size_t)arow * 128 + 2 * kp);
    uint32_t hi, lo;
    split2(v, hi, lo);
    int r = m & 15, mt = m >> 4, kt = kp >> 3;
    int al = (r & 7) * 4 + (kp & 3);
    int j = (r >> 3) + ((kp >> 2) & 1) * 2;
    int slot = A_FRAG(mt, kt, al, j);
    sAh[slot] = hi;
    sAl[slot] = lo;
  }
  __syncthreads();

  const int mw = wid & 3;
  const int nw = wid >> 2;
  float c[2][8][4];
#pragma unroll
  for (int mi = 0; mi < 2; mi++)
#pragma unroll
    for (int nt = 0; nt < 8; nt++)
#pragma unroll
      for (int q = 0; q < 4; q++) c[mi][nt][q] = 0.f;

#pragma unroll
  for (int kt = 0; kt < 8; kt++) {
    uint32_t ah[2][4], al_[2][4];
#pragma unroll
    for (int mi = 0; mi < 2; mi++) {
      *(uint4*)ah[mi]  = *(const uint4*)&sAh[A_FRAG(mw * 2 + mi, kt, lane, 0)];
      *(uint4*)al_[mi] = *(const uint4*)&sAl[A_FRAG(mw * 2 + mi, kt, lane, 0)];
    }
#pragma unroll
    for (int nh = 0; nh < 2; nh++) {
      uint32_t bh[4][2], bl_[4][2];
#pragma unroll
      for (int nt = 0; nt < 4; nt++) {
        int ntile = nw * 8 + nh * 4 + nt;
        int slot = ((kt * 16 + ntile) * 32 + lane) * 2;
        *(uint2*)bh[nt]  = __ldg((const uint2*)&Bh[slot]);
        *(uint2*)bl_[nt] = __ldg((const uint2*)&Bl[slot]);
      }
#pragma unroll
      for (int mi = 0; mi < 2; mi++)
#pragma unroll
        for (int nt = 0; nt < 4; nt++) {
          float* cc = c[mi][nh * 4 + nt];
          mma_bf16(cc, ah[mi], bh[nt]);
          mma_bf16(cc, ah[mi], bl_[nt]);
          mma_bf16(cc, al_[mi], bh[nt]);
        }
    }
  }

#pragma unroll
  for (int mi = 0; mi < 2; mi++) {
    int r0 = bm + mw * 32 + mi * 16 + (lane >> 2);
    int r1 = r0 + 8;
    float s0 = (r0 < M) ? g_dinv[r0] : 0.f;
    float s1 = (r1 < M) ? g_dinv[r1] : 0.f;
#pragma unroll
    for (int nt = 0; nt < 8; nt++) {
      int col = (nw * 8 + nt) * 8 + (lane & 3) * 2;
      if (r0 < M)
        *(float2*)(g_g + (size_t)r0 * 128 + col) =
            make_float2(c[mi][nt][0] * s0, c[mi][nt][1] * s0);
      if (r1 < M)
        *(float2*)(g_g + (size_t)r1 * 128 + col) =
            make_float2(c[mi][nt][2] * s1, c[mi][nt][3] * s1);
    }
  }
}

// ---------------- fragment-input GEMM (layers 1..3): no smem, no sync ------

template <int NT, int DOUT>
__global__ __launch_bounds__(256, 2)
void k_gemm_frag(const uint32_t* __restrict__ Bh, const uint32_t* __restrict__ Bl,
                 int M) {
  const int tid = threadIdx.x;
  const int wid = tid >> 5;
  const int lane = tid & 31;
  const int bm = blockIdx.x * 128;
  const uint32_t* Afh = g_afh + (size_t)blockIdx.x * 8192;
  const uint32_t* Afl = g_afl + (size_t)blockIdx.x * 8192;
  constexpr int WNT = NT / 2;

  const int mw = wid & 3;
  const int nw = wid >> 2;
  float c[2][WNT][4];
#pragma unroll
  for (int mi = 0; mi < 2; mi++)
#pragma unroll
    for (int nt = 0; nt < WNT; nt++)
#pragma unroll
      for (int q = 0; q < 4; q++) c[mi][nt][q] = 0.f;

#pragma unroll
  for (int kt = 0; kt < 8; kt++) {
    uint32_t ah[2][4], al_[2][4];
#pragma unroll
    for (int mi = 0; mi < 2; mi++) {
      int slot = A_FRAG(mw * 2 + mi, kt, lane, 0);
      *(uint4*)ah[mi]  = __ldg((const uint4*)&Afh[slot]);
      *(uint4*)al_[mi] = __ldg((const uint4*)&Afl[slot]);
    }
#pragma unroll
    for (int nh = 0; nh < WNT / 4; nh++) {
      uint32_t bh[4][2], bl_[4][2];
#pragma unroll
      for (int nt = 0; nt < 4; nt++) {
        int ntile = nw * WNT + nh * 4 + nt;
        int slot = ((kt * NT + ntile) * 32 + lane) * 2;
        *(uint2*)bh[nt]  = __ldg((const uint2*)&Bh[slot]);
        *(uint2*)bl_[nt] = __ldg((const uint2*)&Bl[slot]);
      }
#pragma unroll
      for (int mi = 0; mi < 2; mi++)
#pragma unroll
        for (int nt = 0; nt < 4; nt++) {
          float* cc = c[mi][nh * 4 + nt];
          mma_bf16(cc, ah[mi], bh[nt]);
          mma_bf16(cc, ah[mi], bl_[nt]);
          mma_bf16(cc, al_[mi], bh[nt]);
        }
    }
  }

#pragma unroll
  for (int mi = 0; mi < 2; mi++) {
    int r0 = bm + mw * 32 + mi * 16 + (lane >> 2);
    int r1 = r0 + 8;
    float s0 = (r0 < M) ? g_dinv[r0] : 0.f;
    float s1 = (r1 < M) ? g_dinv[r1] : 0.f;
#pragma unroll
    for (int nt = 0; nt < WNT; nt++) {
      int col = (nw * WNT + nt) * 8 + (lane & 3) * 2;
      if (col >= DOUT) continue;
      if (r0 < M)
        *(float2*)(g_g + (size_t)r0 * DOUT + col) =
            make_float2(c[mi][nt][0] * s0, c[mi][nt][1] * s0);
      if (r1 < M)
        *(float2*)(g_g + (size_t)r1 * DOUT + col) =
            make_float2(c[mi][nt][2] * s1, c[mi][nt][3] * s1);
    }
  }
}

// ---------------- CSR gather -> next layer's A fragments ----------------

__global__ void k_gather_frag(const float* __restrict__ bias, int n) {
  int w    = (blockIdx.x * blockDim.x + threadIdx.x) >> 5;
  int lane = threadIdx.x & 31;
  if (w >= n) return;
  int beg = __ldg(g_rowptr + w);
  int end = __ldg(g_rowptr + w + 1);
  float4 acc = *(const float4*)(g_g + (size_t)w * 128 + lane * 4);
  int e = beg;
  for (; e + 4 <= end; e += 4) {
    int s0 = __ldg(g_eidx + e);
    int s1 = __ldg(g_eidx + e + 1);
    int s2 = __ldg(g_eidx + e + 2);
    int s3 = __ldg(g_eidx + e + 3);
    float4 v0 = __ldg((const float4*)(g_g + (size_t)s0 * 128 + lane * 4));
    float4 v1 = __ldg((const float4*)(g_g + (size_t)s1 * 128 + lane * 4));
    float4 v2 = __ldg((const float4*)(g_g + (size_t)s2 * 128 + lane * 4));
    float4 v3 = __ldg((const float4*)(g_g + (size_t)s3 * 128 + lane * 4));
    acc.x += v0.x; acc.y += v0.y; acc.z += v0.z; acc.w += v0.w;
    acc.x += v1.x; acc.y += v1.y; acc.z += v1.z; acc.w += v1.w;
    acc.x += v2.x; acc.y += v2.y; acc.z += v2.z; acc.w += v2.w;
    acc.x += v3.x; acc.y += v3.y; acc.z += v3.z; acc.w += v3.w;
  }
  for (; e < end; e++) {
    int s = __ldg(g_eidx + e);
    float4 v = __ldg((const float4*)(g_g + (size_t)s * 128 + lane * 4));
    acc.x += v.x; acc.y += v.y; acc.z += v.z; acc.w += v.w;
  }
  float sc = g_dinv[w];
  float4 b = *(const float4*)(bias + lane * 4);
  float h0 = fmaxf(acc.x * sc + b.x, 0.f);
  float h1 = fmaxf(acc.y * sc + b.y, 0.f);
  float h2 = fmaxf(acc.z * sc + b.z, 0.f);
  float h3 = fmaxf(acc.w * sc + b.w, 0.f);
  uint32_t hA, lA, hB, lB;
  split2(make_float2(h0, h1), hA, lA);
  split2(make_float2(h2, h3), hB, lB);
  int block = w >> 7, mloc = w & 127;
  int r = mloc & 15, mt = mloc >> 4;
  int kt = lane >> 2;
  int fl0 = (r & 7) * 4 + ((2 * lane) & 3);
  int j = (r >> 3) + ((lane >> 1) & 1) * 2;
  size_t slot0 = (size_t)block * 8192 + A_FRAG(mt, kt, fl0, j);
  g_afh[slot0]     = hA;
  g_afh[slot0 + 4] = hB;
  g_afl[slot0]     = lA;
  g_afl[slot0 + 4] = lB;
}

// last layer (D=40): gather + finalize fused, 10 threads/node -> d_out.
__global__ void k_gather_out(const float* __restrict__ bias,
                             float* __restrict__ out, int n) {
  int t    = blockIdx.x * blockDim.x + threadIdx.x;
  int node = t / 10;
  int lane = t - node * 10;
  if (node >= n) return;
  int c = lane * 4;
  int beg = __ldg(g_rowptr + node);
  int end = __ldg(g_rowptr + node + 1);
  float4 acc = *(const float4*)(g_g + (size_t)node * 40 + c);
  int e = beg;
  for (; e + 4 <= end; e += 4) {
    int s0 = __ldg(g_eidx + e);
    int s1 = __ldg(g_eidx + e + 1);
    int s2 = __ldg(g_eidx + e + 2);
    int s3 = __ldg(g_eidx + e + 3);
    float4 v0 = __ldg((const float4*)(g_g + (size_t)s0 * 40 + c));
    float4 v1 = __ldg((const float4*)(g_g + (size_t)s1 * 40 + c));
    float4 v2 = __ldg((const float4*)(g_g + (size_t)s2 * 40 + c));
    float4 v3 = __ldg((const float4*)(g_g + (size_t)s3 * 40 + c));
    acc.x += v0.x; acc.y += v0.y; acc.z += v0.z; acc.w += v0.w;
    acc.x += v1.x; acc.y += v1.y; acc.z += v1.z; acc.w += v1.w;
    acc.x += v2.x; acc.y += v2.y; acc.z += v2.z; acc.w += v2.w;
    acc.x += v3.x; acc.y += v3.y; acc.z += v3.z; acc.w += v3.w;
  }
  for (; e < end; e++) {
    int s = __ldg(g_eidx + e);
    float4 v = __ldg((const float4*)(g_g + (size_t)s * 40 + c));
    acc.x += v.x; acc.y += v.y; acc.z += v.z; acc.w += v.w;
  }
  float sc = g_dinv[node];
  float4 b = *(const float4*)(bias + c);
  acc.x = acc.x * sc + b.x;
  acc.y = acc.y * sc + b.y;
  acc.z = acc.z * sc + b.z;
  acc.w = acc.w * sc + b.w;
  *(float4*)(out + (size_t)node * 40 + c) = acc;
}

// ---------------- host launcher ----------------

extern "C" void kernel_launch(void* const* d_in, const int* in_sizes, int n_in,
                              void* d_out, int out_size) {
  const float* x  = (const float*)d_in[0];
  const int*   ei = (const int*)d_in[1];
  const float* W[4] = {(const float*)d_in[2], (const float*)d_in[4],
                       (const float*)d_in[6], (const float*)d_in[8]};
  const float* b[4] = {(const float*)d_in[3], (const float*)d_in[5],
                       (const float*)d_in[7], (const float*)d_in[9]};

  int M = in_sizes[0] / FD;  // 100000
  int E = in_sizes[1] / 2;   // 500000
  const int* src = ei;
  const int* dst = ei + E;

  uint32_t *wfh, *wfl, *w3h, *w3l;
  cudaGetSymbolAddress((void**)&wfh, g_wfh);
  cudaGetSymbolAddress((void**)&wfl, g_wfl);
  cudaGetSymbolAddress((void**)&w3h, g_w3h);
  cudaGetSymbolAddress((void**)&w3l, g_w3l);

  const int SMEM = 65536;
  cudaFuncSetAttribute((const void*)k_gemm_l0,
                       cudaFuncAttributeMaxDynamicSharedMemorySize, SMEM);

  int nscan = (M + SCAN_B - 1) / SCAN_B;  // 196
  int GB = (M + 127) / 128;               // 782
  int gatherB = (M * 32 + 255) / 256;     // 12500
  int initB = (28672 + M + 255) / 256;

  // 1: W frags + zero cnt
  k_init<<<initB, 256>>>(W[0], W[1], W[2], W[3], M);
  // 2: degree count
  k_count<<<(E + 255) / 256, 256>>>(dst, E);
  // 3: scan1 (also computes dinv)
  k_scan1<<<nscan, SCAN_B>>>(M);
  // 4: layer-0 GEMM  (ncu profiles launch #4; needs dinv + W0 frags)
  k_gemm_l0<<<GB, 256, SMEM>>>(x, wfh, wfl, M);
  // 5-6: finish CSR
  k_scan23<<<nscan, SCAN_B>>>(M);
  k_fill<<<(E + 255) / 256, 256>>>(src, dst, E);

  // layer 0 aggregate -> A frags for layer 1
  k_gather_frag<<<gatherB, 256>>>(b[0], M);
  // layers 1-2
  k_gemm_frag<16, 128><<<GB, 256>>>(wfh + 8192, wfl + 8192, M);
  k_gather_frag<<<gatherB, 256>>>(b[1], M);
  k_gemm_frag<16, 128><<<GB, 256>>>(wfh + 16384, wfl + 16384, M);
  k_gather_frag<<<gatherB, 256>>>(b[2], M);
  // layer 3: D=40 frag GEMM + fused gather/finalize -> d_out
  k_gemm_frag<8, 40><<<GB, 256>>>(w3h, w3l, M);
  k_gather_out<<<(M * 10 + 255) / 256, 256>>>(b[3], (float*)d_out, M);
}

// round 17
// speedup vs baseline: 1.0724x; 1.0372x over previous
#include <cuda_runtime.h>
#include <cuda_bf16.h>
#include <cstdint>

// GCN, 4 layers: h' = relu( D^-1/2 (A+I) D^-1/2 (h W) + b )
// All GEMMs on mma.sync bf16x3 (D = AhBh+AhBl+AlBh, fp32 accum, ~6e-6 err).
// W fragments pre-converted once (k_init). The CSR gather applies
// relu(agg*dinv+bias), splits to bf16 hi/lo and writes the NEXT layer's
// A-FRAGMENTS directly -> follow-on GEMMs (k_gemm_frag) are pure LDG + MMA.
// Layer-0 GEMM stages A through smem (cross-warp reuse; batched convert).
// NEW: CSR build (scan1/scan23/fill) forked onto a side stream and overlapped
// with the layer-0 GEMM via events (graph-capture-safe fork/join).

#define NN 100000
#define EE 500000
#define FD 128
#define NBLK 782  // ceil(NN/128)

__device__ float g_dinv[NN];
__device__ float g_g[(size_t)NN * FD];
// CSR (dst-major)
__device__ int g_cnt[NN];
__device__ int g_rowptr[NN + 1];
__device__ int g_fill[NN];
__device__ int g_eidx[EE];
__device__ int g_bsums[256];
// W fragments (hi/lo): 3 wide layers x 8192, narrow 4096
__device__ uint32_t g_wfh[3][8192];
__device__ uint32_t g_wfl[3][8192];
__device__ uint32_t g_w3h[4096];
__device__ uint32_t g_w3l[4096];
// A fragments written by the gather (zero-init covers pad rows)
__device__ uint32_t g_afh[(size_t)NBLK * 8192];
__device__ uint32_t g_afl[(size_t)NBLK * 8192];

// side stream + events, created once at load time (host objects only; no
// device memory, no per-call static guards).
static cudaStream_t g_s2;
static cudaEvent_t g_evC, g_evF;
namespace {
struct StreamInit {
  StreamInit() {
    cudaStreamCreateWithFlags(&g_s2, cudaStreamNonBlocking);
    cudaEventCreateWithFlags(&g_evC, cudaEventDisableTiming);
    cudaEventCreateWithFlags(&g_evF, cudaEventDisableTiming);
  }
};
StreamInit g_stream_init;
}  // namespace

// ---------------- fragment layout ----------------
//   A: [mtile 8][ktile 8][lane 32][j 4]   (m16k16 row-major A fragment)
//   B: [ktile 8][ntile NT][lane 32][j 2]  (k16n8 col-major B fragment)
#define A_FRAG(mt, kt, lane, j) ((((mt) * 8 + (kt)) * 32 + (lane)) * 4 + (j))

__device__ __forceinline__ uint32_t pack_bf16(float x, float y) {
  __nv_bfloat162 p = __floats2bfloat162_rn(x, y);  // x -> low half
  return *(uint32_t*)&p;
}

__device__ __forceinline__ void mma_bf16(float* c, const uint32_t* a,
                                         const uint32_t* b) {
  asm volatile(
      "mma.sync.aligned.m16n8k16.row.col.f32.bf16.bf16.f32 "
      "{%0,%1,%2,%3}, {%4,%5,%6,%7}, {%8,%9}, {%0,%1,%2,%3};"
      : "+f"(c[0]), "+f"(c[1]), "+f"(c[2]), "+f"(c[3])
      : "r"(a[0]), "r"(a[1]), "r"(a[2]), "r"(a[3]), "r"(b[0]), "r"(b[1]));
}

// split a float2 (k-consecutive pair) into packed hi / lo bf16x2
__device__ __forceinline__ void split2(float2 v, uint32_t& hi, uint32_t& lo) {
  __nv_bfloat16 h0 = __float2bfloat16(v.x), h1 = __float2bfloat16(v.y);
  float l0 = v.x - __bfloat162float(h0), l1 = v.y - __bfloat162float(h1);
  hi = pack_bf16(__bfloat162float(h0), __bfloat162float(h1));
  lo = pack_bf16(l0, l1);
}

// ---------------- init: W fragment prep + cnt zeroing (fused) ----------------

__global__ void k_init(const float* __restrict__ W0, const float* __restrict__ W1,
                       const float* __restrict__ W2, const float* __restrict__ W3,
                       int n) {
  int idx = blockIdx.x * blockDim.x + threadIdx.x;
  if (idx < 28672) {
    int D, NT, lidx;
    const float* W;
    uint32_t *fh, *fl;
    if (idx < 24576) {
      int l = idx >> 13;
      lidx = idx & 8191;
      D = 128; NT = 16;
      W = (l == 0) ? W0 : (l == 1) ? W1 : W2;
      fh = g_wfh[l]; fl = g_wfl[l];
    } else {
      lidx = idx - 24576;
      D = 40; NT = 8;
      W = W3;
      fh = g_w3h; fl = g_w3l;
    }
    int ncols = NT * 8;
    int nn = lidx % ncols;
    int kp = lidx / ncols;  // k pair 0..63
    float2 v = make_float2(0.f, 0.f);
    if (nn < D) {
      v.x = W[(size_t)(2 * kp) * D + nn];
      v.y = W[(size_t)(2 * kp + 1) * D + nn];
    }
    uint32_t hi, lo;
    split2(v, hi, lo);
    int kt = kp >> 3;
    int lane = (nn & 7) * 4 + (kp & 3);
    int j = (kp >> 2) & 1;
    int slot = (((kt * NT) + (nn >> 3)) * 32 + lane) * 2 + j;
    fh[slot] = hi;
    fl[slot] = lo;
  } else {
    int i = idx - 28672;
    if (i < n) g_cnt[i] = 0;
  }
}

// ---------------- degree + CSR build ----------------

__global__ void k_count(const int* __restrict__ dst, int e) {
  int i = blockIdx.x * blockDim.x + threadIdx.x;
  if (i < e) atomicAdd(&g_cnt[dst[i]], 1);
}
__global__ void k_dinv(int n) {
  int i = blockIdx.x * blockDim.x + threadIdx.x;
  if (i < n) g_dinv[i] = rsqrtf((float)(1 + g_cnt[i]));  // +1 self loop
}

#define SCAN_B 512
__global__ void k_scan1(int n) {  // block-local inclusive scan -> rowptr[i+1]
  __shared__ int sm[SCAN_B];
  int i = blockIdx.x * SCAN_B + threadIdx.x;
  sm[threadIdx.x] = (i < n) ? g_cnt[i] : 0;
  __syncthreads();
  for (int off = 1; off < SCAN_B; off <<= 1) {
    int t = (threadIdx.x >= off) ? sm[threadIdx.x - off] : 0;
    __syncthreads();
    sm[threadIdx.x] += t;
    __syncthreads();
  }
  if (i < n) g_rowptr[i + 1] = sm[threadIdx.x];
  if (threadIdx.x == SCAN_B - 1) g_bsums[blockIdx.x] = sm[threadIdx.x];
  if (i == 0) g_rowptr[0] = 0;
}

// scan2+scan3 merged: each block reduces its own bsums prefix inline.
__global__ void k_scan23(int n) {
  __shared__ int red[256];
  __shared__ int base_sh;
  int t = threadIdx.x;
  if (t < 256) red[t] = (t < (int)blockIdx.x) ? g_bsums[t] : 0;
  __syncthreads();
#pragma unroll
  for (int off = 128; off > 0; off >>= 1) {
    if (t < off) red[t] += red[t + off];
    __syncthreads();
  }
  if (t == 0) base_sh = red[0];
  __syncthreads();
  int base = base_sh;
  int i = blockIdx.x * SCAN_B + t;
  if (i < n) {
    int v = g_rowptr[i + 1] + base;
    g_rowptr[i + 1] = v;
    if (i + 1 < n) g_fill[i + 1] = v;  // fill[i] = rowptr[i]
    if (i == 0) g_fill[0] = 0;
  }
}
__global__ void k_fill(const int* __restrict__ src, const int* __restrict__ dst,
                       int e) {
  int i = blockIdx.x * blockDim.x + threadIdx.x;
  if (i < e) {
    int p = atomicAdd(&g_fill[dst[i]], 1);
    g_eidx[p] = src[i];
  }
}

// ---------------- layer-0 GEMM (smem staging, batched convert) ----------------

__global__ __launch_bounds__(256, 2)
void k_gemm_l0(const float* __restrict__ A, const uint32_t* __restrict__ Bh,
               const uint32_t* __restrict__ Bl, int M) {
  extern __shared__ uint32_t sm[];
  uint32_t* sAh = sm;  // 8192 u32
  uint32_t* sAl = sm + 8192;

  const int tid = threadIdx.x;
  const int wid = tid >> 5;
  const int lane = tid & 31;
  const int bm = blockIdx.x * 128;

#pragma unroll
  for (int it = 0; it < 32; it++) {
    int idx = it * 256 + tid;
    int m = idx >> 6;
    int kp = idx & 63;
    int arow = bm + m;
    float2 v = make_float2(0.f, 0.f);
    if (arow < M) v = *(const float2*)(A + (size_t)arow * 128 + 2 * kp);
    uint32_t hi, lo;
    split2(v, hi, lo);
    int r = m & 15, mt = m >> 4, kt = kp >> 3;
    int al = (r & 7) * 4 + (kp & 3);
    int j = (r >> 3) + ((kp >> 2) & 1) * 2;
    int slot = A_FRAG(mt, kt, al, j);
    sAh[slot] = hi;
    sAl[slot] = lo;
  }
  __syncthreads();

  const int mw = wid & 3;
  const int nw = wid >> 2;
  float c[2][8][4];
#pragma unroll
  for (int mi = 0; mi < 2; mi++)
#pragma unroll
    for (int nt = 0; nt < 8; nt++)
#pragma unroll
      for (int q = 0; q < 4; q++) c[mi][nt][q] = 0.f;

#pragma unroll
  for (int kt = 0; kt < 8; kt++) {
    uint32_t ah[2][4], al_[2][4];
#pragma unroll
    for (int mi = 0; mi < 2; mi++) {
      *(uint4*)ah[mi]  = *(const uint4*)&sAh[A_FRAG(mw * 2 + mi, kt, lane, 0)];
      *(uint4*)al_[mi] = *(const uint4*)&sAl[A_FRAG(mw * 2 + mi, kt, lane, 0)];
    }
#pragma unroll
    for (int nh = 0; nh < 2; nh++) {
      uint32_t bh[4][2], bl_[4][2];
#pragma unroll
      for (int nt = 0; nt < 4; nt++) {
        int ntile = nw * 8 + nh * 4 + nt;
        int slot = ((kt * 16 + ntile) * 32 + lane) * 2;
        *(uint2*)bh[nt]  = __ldg((const uint2*)&Bh[slot]);
        *(uint2*)bl_[nt] = __ldg((const uint2*)&Bl[slot]);
      }
#pragma unroll
      for (int mi = 0; mi < 2; mi++)
#pragma unroll
        for (int nt = 0; nt < 4; nt++) {
          float* cc = c[mi][nh * 4 + nt];
          mma_bf16(cc, ah[mi], bh[nt]);
          mma_bf16(cc, ah[mi], bl_[nt]);
          mma_bf16(cc, al_[mi], bh[nt]);
        }
    }
  }

#pragma unroll
  for (int mi = 0; mi < 2; mi++) {
    int r0 = bm + mw * 32 + mi * 16 + (lane >> 2);
    int r1 = r0 + 8;
    float s0 = (r0 < M) ? g_dinv[r0] : 0.f;
    float s1 = (r1 < M) ? g_dinv[r1] : 0.f;
#pragma unroll
    for (int nt = 0; nt < 8; nt++) {
      int col = (nw * 8 + nt) * 8 + (lane & 3) * 2;
      if (r0 < M)
        *(float2*)(g_g + (size_t)r0 * 128 + col) =
            make_float2(c[mi][nt][0] * s0, c[mi][nt][1] * s0);
      if (r1 < M)
        *(float2*)(g_g + (size_t)r1 * 128 + col) =
            make_float2(c[mi][nt][2] * s1, c[mi][nt][3] * s1);
    }
  }
}

// ---------------- fragment-input GEMM (layers 1..3): no smem, no sync ------

template <int NT, int DOUT>
__global__ __launch_bounds__(256, 2)
void k_gemm_frag(const uint32_t* __restrict__ Bh, const uint32_t* __restrict__ Bl,
                 int M) {
  const int tid = threadIdx.x;
  const int wid = tid >> 5;
  const int lane = tid & 31;
  const int bm = blockIdx.x * 128;
  const uint32_t* Afh = g_afh + (size_t)blockIdx.x * 8192;
  const uint32_t* Afl = g_afl + (size_t)blockIdx.x * 8192;
  constexpr int WNT = NT / 2;

  const int mw = wid & 3;
  const int nw = wid >> 2;
  float c[2][WNT][4];
#pragma unroll
  for (int mi = 0; mi < 2; mi++)
#pragma unroll
    for (int nt = 0; nt < WNT; nt++)
#pragma unroll
      for (int q = 0; q < 4; q++) c[mi][nt][q] = 0.f;

#pragma unroll
  for (int kt = 0; kt < 8; kt++) {
    uint32_t ah[2][4], al_[2][4];
#pragma unroll
    for (int mi = 0; mi < 2; mi++) {
      int slot = A_FRAG(mw * 2 + mi, kt, lane, 0);
      *(uint4*)ah[mi]  = __ldg((const uint4*)&Afh[slot]);
      *(uint4*)al_[mi] = __ldg((const uint4*)&Afl[slot]);
    }
#pragma unroll
    for (int nh = 0; nh < WNT / 4; nh++) {
      uint32_t bh[4][2], bl_[4][2];
#pragma unroll
      for (int nt = 0; nt < 4; nt++) {
        int ntile = nw * WNT + nh * 4 + nt;
        int slot = ((kt * NT + ntile) * 32 + lane) * 2;
        *(uint2*)bh[nt]  = __ldg((const uint2*)&Bh[slot]);
        *(uint2*)bl_[nt] = __ldg((const uint2*)&Bl[slot]);
      }
#pragma unroll
      for (int mi = 0; mi < 2; mi++)
#pragma unroll
        for (int nt = 0; nt < 4; nt++) {
          float* cc = c[mi][nh * 4 + nt];
          mma_bf16(cc, ah[mi], bh[nt]);
          mma_bf16(cc, ah[mi], bl_[nt]);
          mma_bf16(cc, al_[mi], bh[nt]);
        }
    }
  }

#pragma unroll
  for (int mi = 0; mi < 2; mi++) {
    int r0 = bm + mw * 32 + mi * 16 + (lane >> 2);
    int r1 = r0 + 8;
    float s0 = (r0 < M) ? g_dinv[r0] : 0.f;
    float s1 = (r1 < M) ? g_dinv[r1] : 0.f;
#pragma unroll
    for (int nt = 0; nt < WNT; nt++) {
      int col = (nw * WNT + nt) * 8 + (lane & 3) * 2;
      if (col >= DOUT) continue;
      if (r0 < M)
        *(float2*)(g_g + (size_t)r0 * DOUT + col) =
            make_float2(c[mi][nt][0] * s0, c[mi][nt][1] * s0);
      if (r1 < M)
        *(float2*)(g_g + (size_t)r1 * DOUT + col) =
            make_float2(c[mi][nt][2] * s1, c[mi][nt][3] * s1);
    }
  }
}

// ---------------- CSR gather -> next layer's A fragments ----------------

__global__ void k_gather_frag(const float* __restrict__ bias, int n) {
  int w    = (blockIdx.x * blockDim.x + threadIdx.x) >> 5;
  int lane = threadIdx.x & 31;
  if (w >= n) return;
  int beg = __ldg(g_rowptr + w);
  int end = __ldg(g_rowptr + w + 1);
  float4 acc = *(const float4*)(g_g + (size_t)w * 128 + lane * 4);
  int e = beg;
  for (; e + 4 <= end; e += 4) {
    int s0 = __ldg(g_eidx + e);
    int s1 = __ldg(g_eidx + e + 1);
    int s2 = __ldg(g_eidx + e + 2);
    int s3 = __ldg(g_eidx + e + 3);
    float4 v0 = __ldg((const float4*)(g_g + (size_t)s0 * 128 + lane * 4));
    float4 v1 = __ldg((const float4*)(g_g + (size_t)s1 * 128 + lane * 4));
    float4 v2 = __ldg((const float4*)(g_g + (size_t)s2 * 128 + lane * 4));
    float4 v3 = __ldg((const float4*)(g_g + (size_t)s3 * 128 + lane * 4));
    acc.x += v0.x; acc.y += v0.y; acc.z += v0.z; acc.w += v0.w;
    acc.x += v1.x; acc.y += v1.y; acc.z += v1.z; acc.w += v1.w;
    acc.x += v2.x; acc.y += v2.y; acc.z += v2.z; acc.w += v2.w;
    acc.x += v3.x; acc.y += v3.y; acc.z += v3.z; acc.w += v3.w;
  }
  for (; e < end; e++) {
    int s = __ldg(g_eidx + e);
    float4 v = __ldg((const float4*)(g_g + (size_t)s * 128 + lane * 4));
    acc.x += v.x; acc.y += v.y; acc.z += v.z; acc.w += v.w;
  }
  float sc = g_dinv[w];
  float4 b = *(const float4*)(bias + lane * 4);
  float h0 = fmaxf(acc.x * sc + b.x, 0.f);
  float h1 = fmaxf(acc.y * sc + b.y, 0.f);
  float h2 = fmaxf(acc.z * sc + b.z, 0.f);
  float h3 = fmaxf(acc.w * sc + b.w, 0.f);
  uint32_t hA, lA, hB, lB;
  split2(make_float2(h0, h1), hA, lA);
  split2(make_float2(h2, h3), hB, lB);
  int block = w >> 7, mloc = w & 127;
  int r = mloc & 15, mt = mloc >> 4;
  int kt = lane >> 2;
  int fl0 = (r & 7) * 4 + ((2 * lane) & 3);
  int j = (r >> 3) + ((lane >> 1) & 1) * 2;
  size_t slot0 = (size_t)block * 8192 + A_FRAG(mt, kt, fl0, j);
  g_afh[slot0]     = hA;
  g_afh[slot0 + 4] = hB;
  g_afl[slot0]     = lA;
  g_afl[slot0 + 4] = lB;
}

// last layer (D=40): gather + finalize fused, 10 threads/node -> d_out.
__global__ void k_gather_out(const float* __restrict__ bias,
                             float* __restrict__ out, int n) {
  int t    = blockIdx.x * blockDim.x + threadIdx.x;
  int node = t / 10;
  int lane = t - node * 10;
  if (node >= n) return;
  int c = lane * 4;
  int beg = __ldg(g_rowptr + node);
  int end = __ldg(g_rowptr + node + 1);
  float4 acc = *(const float4*)(g_g + (size_t)node * 40 + c);
  int e = beg;
  for (; e + 4 <= end; e += 4) {
    int s0 = __ldg(g_eidx + e);
    int s1 = __ldg(g_eidx + e + 1);
    int s2 = __ldg(g_eidx + e + 2);
    int s3 = __ldg(g_eidx + e + 3);
    float4 v0 = __ldg((const float4*)(g_g + (size_t)s0 * 40 + c));
    float4 v1 = __ldg((const float4*)(g_g + (size_t)s1 * 40 + c));
    float4 v2 = __ldg((const float4*)(g_g + (size_t)s2 * 40 + c));
    float4 v3 = __ldg((const float4*)(g_g + (size_t)s3 * 40 + c));
    acc.x += v0.x; acc.y += v0.y; acc.z += v0.z; acc.w += v0.w;
    acc.x += v1.x; acc.y += v1.y; acc.z += v1.z; acc.w += v1.w;
    acc.x += v2.x; acc.y += v2.y; acc.z += v2.z; acc.w += v2.w;
    acc.x += v3.x; acc.y += v3.y; acc.z += v3.z; acc.w += v3.w;
  }
  for (; e < end; e++) {
    int s = __ldg(g_eidx + e);
    float4 v = __ldg((const float4*)(g_g + (size_t)s * 40 + c));
    acc.x += v.x; acc.y += v.y; acc.z += v.z; acc.w += v.w;
  }
  float sc = g_dinv[node];
  float4 b = *(const float4*)(bias + c);
  acc.x = acc.x * sc + b.x;
  acc.y = acc.y * sc + b.y;
  acc.z = acc.z * sc + b.z;
  acc.w = acc.w * sc + b.w;
  *(float4*)(out + (size_t)node * 40 + c) = acc;
}

// ---------------- host launcher ----------------

extern "C" void kernel_launch(void* const* d_in, const int* in_sizes, int n_in,
                              void* d_out, int out_size) {
  const float* x  = (const float*)d_in[0];
  const int*   ei = (const int*)d_in[1];
  const float* W[4] = {(const float*)d_in[2], (const float*)d_in[4],
                       (const float*)d_in[6], (const float*)d_in[8]};
  const float* b[4] = {(const float*)d_in[3], (const float*)d_in[5],
                       (const float*)d_in[7], (const float*)d_in[9]};

  int M = in_sizes[0] / FD;  // 100000
  int E = in_sizes[1] / 2;   // 500000
  const int* src = ei;
  const int* dst = ei + E;

  uint32_t *wfh, *wfl, *w3h, *w3l;
  cudaGetSymbolAddress((void**)&wfh, g_wfh);
  cudaGetSymbolAddress((void**)&wfl, g_wfl);
  cudaGetSymbolAddress((void**)&w3h, g_w3h);
  cudaGetSymbolAddress((void**)&w3l, g_w3l);

  const int SMEM = 65536;
  cudaFuncSetAttribute((const void*)k_gemm_l0,
                       cudaFuncAttributeMaxDynamicSharedMemorySize, SMEM);

  int nscan = (M + SCAN_B - 1) / SCAN_B;  // 196
  int GB = (M + 127) / 128;               // 782
  int gatherB = (M * 32 + 255) / 256;     // 12500
  int initB = (28672 + M + 255) / 256;

  // default stream: init -> count -> dinv -> l0 GEMM
  k_init<<<initB, 256>>>(W[0], W[1], W[2], W[3], M);
  k_count<<<(E + 255) / 256, 256>>>(dst, E);
  cudaEventRecord(g_evC, 0);               // cnt final
  k_dinv<<<(M + 255) / 256, 256>>>(M);
  k_gemm_l0<<<GB, 256, SMEM>>>(x, wfh, wfl, M);   // launch #4 for ncu

  // side stream: CSR build (scan1 -> scan23 -> fill), overlapped with l0
  cudaStreamWaitEvent(g_s2, g_evC, 0);
  k_scan1<<<nscan, SCAN_B, 0, g_s2>>>(M);
  k_scan23<<<nscan, SCAN_B, 0, g_s2>>>(M);
  k_fill<<<(E + 255) / 256, 256, 0, g_s2>>>(src, dst, E);
  cudaEventRecord(g_evF, g_s2);
  cudaStreamWaitEvent(0, g_evF, 0);        // join before gathers

  // layer 0 aggregate -> A frags for layer 1
  k_gather_frag<<<gatherB, 256>>>(b[0], M);
  // layers 1-2
  k_gemm_frag<16, 128><<<GB, 256>>>(wfh + 8192, wfl + 8192, M);
  k_gather_frag<<<gatherB, 256>>>(b[1], M);
  k_gemm_frag<16, 128><<<GB, 256>>>(wfh + 16384, wfl + 16384, M);
  k_gather_frag<<<gatherB, 256>>>(b[2], M);
  // layer 3: D=40 frag GEMM + fused gather/finalize -> d_out
  k_gemm_frag<8, 40><<<GB, 256>>>(w3h, w3l, M);
  k_gather_out<<<(M * 10 + 255) / 256, 256>>>(b[3], (float*)d_out, M);
}